// round 15
// baseline (speedup 1.0000x reference)
#include <cuda_runtime.h>
#include <cuda_bf16.h>
#include <cstdint>

#define HEADS 16
#define NTOK  64
#define CDIM  512
#define BATCH 1024
#define MROWS (BATCH*NTOK)

// ---- device scratch ----
__device__ __nv_bfloat16 g_ahi[MROWS*CDIM];
__device__ __nv_bfloat16 g_alo[MROWS*CDIM];
__device__ float         g_Q  [(size_t)MROWS*CDIM];
__device__ float         g_KV [(size_t)MROWS*2*CDIM];
__device__ __nv_bfloat16 g_wq_hi [CDIM*CDIM];
__device__ __nv_bfloat16 g_wq_lo [CDIM*CDIM];
__device__ __nv_bfloat16 g_wkv_hi[2*CDIM*CDIM];
__device__ __nv_bfloat16 g_wkv_lo[2*CDIM*CDIM];
__device__ __nv_bfloat16 g_wp_hi [CDIM*CDIM];
__device__ __nv_bfloat16 g_wp_lo [CDIM*CDIM];
__device__ float         g_bias[HEADS*NTOK*NTOK];

__device__ __forceinline__ void split_pack2(float a, float b, uint32_t& hp, uint32_t& lp) {
    __nv_bfloat16 ha = __float2bfloat16(a), hb = __float2bfloat16(b);
    __nv_bfloat16 la = __float2bfloat16(a - __bfloat162float(ha));
    __nv_bfloat16 lb = __float2bfloat16(b - __bfloat162float(hb));
    hp = (uint32_t)__bfloat16_as_ushort(ha) | ((uint32_t)__bfloat16_as_ushort(hb) << 16);
    lp = (uint32_t)__bfloat16_as_ushort(la) | ((uint32_t)__bfloat16_as_ushort(lb) << 16);
}

__device__ __forceinline__ void mma16816(float* d, const uint32_t* a, const uint32_t* b) {
    asm volatile(
        "mma.sync.aligned.m16n8k16.row.col.f32.bf16.bf16.f32 "
        "{%0,%1,%2,%3}, {%4,%5,%6,%7}, {%8,%9}, {%0,%1,%2,%3};"
        : "+f"(d[0]), "+f"(d[1]), "+f"(d[2]), "+f"(d[3])
        : "r"(a[0]), "r"(a[1]), "r"(a[2]), "r"(a[3]), "r"(b[0]), "r"(b[1]));
}

// ---- kernel: CPB bias MLP (batch independent) ----
__global__ void __launch_bounds__(64) cpb_kernel(const float* __restrict__ w1, const float* __restrict__ b1,
                                                 const float* __restrict__ w2, const float* __restrict__ b2,
                                                 float* __restrict__ bias) {
    int p = blockIdx.x * 64 + threadIdx.x;
    int i = p >> 6, j = p & 63;
    float r0 = (float)((i >> 3) - (j >> 3));
    float r1 = (float)((i & 7) - (j & 7));
    float v0 = (r0 > 0.f ? 1.f : (r0 < 0.f ? -1.f : 0.f)) * log1pf(fabsf(r0));
    float v1 = (r1 > 0.f ? 1.f : (r1 < 0.f ? -1.f : 0.f)) * log1pf(fabsf(r1));
    float acc[16];
#pragma unroll
    for (int h = 0; h < 16; ++h) acc[h] = b2[h];
    for (int c = 0; c < 256; ++c) {
        float hv = fmaxf(v0 * w1[c] + v1 * w1[256 + c] + b1[c], 0.f);
#pragma unroll
        for (int h = 0; h < 16; ++h) acc[h] += hv * w2[c * 16 + h];
    }
#pragma unroll
    for (int h = 0; h < 16; ++h) bias[h * 4096 + p] = acc[h];
}

// ---- kernel: fp32 -> bf16 hi/lo split ----
__global__ void __launch_bounds__(256) split_kernel(const float* __restrict__ X,
                                                    __nv_bfloat16* __restrict__ Hi,
                                                    __nv_bfloat16* __restrict__ Lo, int n4) {
    int idx = blockIdx.x * 256 + threadIdx.x;
    if (idx >= n4) return;
    float4 v = ((const float4*)X)[idx];
    uint32_t h0, h1, l0, l1;
    split_pack2(v.x, v.y, h0, l0);
    split_pack2(v.z, v.w, h1, l1);
    ((uint2*)Hi)[idx] = make_uint2(h0, h1);
    ((uint2*)Lo)[idx] = make_uint2(l0, l1);
}

// ---- kernel: weight transpose + split: WT[n][k] = W[k][n] ----
__global__ void __launch_bounds__(256) wsplit_kernel(const float* __restrict__ W,
                                                     __nv_bfloat16* __restrict__ Hi,
                                                     __nv_bfloat16* __restrict__ Lo, int Nout, int total) {
    int idx = blockIdx.x * 256 + threadIdx.x;
    if (idx >= total) return;
    int k = idx & (CDIM - 1), n = idx >> 9;
    float v = W[(size_t)k * Nout + n];
    __nv_bfloat16 hv = __float2bfloat16(v);
    Hi[idx] = hv;
    Lo[idx] = __float2bfloat16(v - __bfloat162float(hv));
}

// ---- kernel: split-bf16 HMMA GEMM, tile 128x128, Kc=32, K=512 ----
// A: M x 512 bf16 (K-contig). B = W^T: N x 512 bf16 (K-contig). C = A@W + bias (fp32).
#define RS 80   // smem row stride bytes (32 bf16 = 64B data + 16B pad)
__global__ void __launch_bounds__(256) gemm_tc(const __nv_bfloat16* __restrict__ Ahi,
                                               const __nv_bfloat16* __restrict__ Alo,
                                               const __nv_bfloat16* __restrict__ Bhi,
                                               const __nv_bfloat16* __restrict__ Blo,
                                               const float* __restrict__ bias,
                                               float* __restrict__ C, int Nout) {
    __shared__ __align__(16) char sm[4 * 128 * RS];
    char* sAh = sm;
    char* sAl = sm + 128 * RS;
    char* sBh = sm + 2 * 128 * RS;
    char* sBl = sm + 3 * 128 * RS;

    int tid = threadIdx.x, wid = tid >> 5, lane = tid & 31;
    int wr = wid & 3, wc = wid >> 2;            // warp row (M/32), warp col (N/64)
    int g = lane >> 2, tg = lane & 3;
    int n0 = blockIdx.x * 128, m0 = blockIdx.y * 128;

    float acc[2][8][4];
#pragma unroll
    for (int mt = 0; mt < 2; ++mt)
#pragma unroll
        for (int nt = 0; nt < 8; ++nt)
#pragma unroll
            for (int c = 0; c < 4; ++c) acc[mt][nt][c] = 0.f;

    for (int ch = 0; ch < 16; ++ch) {
        int k0 = ch * 32;
        __syncthreads();
#pragma unroll
        for (int it = 0; it < 2; ++it) {
            int idx = tid + it * 256;           // 0..511
            int r = idx >> 2, c16 = idx & 3;    // row, which 16B of 64B row
            size_t ga = (size_t)(m0 + r) * CDIM + k0 + c16 * 8;
            *(uint4*)(sAh + r * RS + c16 * 16) = *(const uint4*)(Ahi + ga);
            *(uint4*)(sAl + r * RS + c16 * 16) = *(const uint4*)(Alo + ga);
            size_t gb = (size_t)(n0 + r) * CDIM + k0 + c16 * 8;
            *(uint4*)(sBh + r * RS + c16 * 16) = *(const uint4*)(Bhi + gb);
            *(uint4*)(sBl + r * RS + c16 * 16) = *(const uint4*)(Blo + gb);
        }
        __syncthreads();

#pragma unroll
        for (int ks = 0; ks < 2; ++ks) {
            int kb = ks * 32 + tg * 4;          // byte offset of this thread's k pair
            uint32_t ah[2][4], al[2][4], bh[8][2], bl[8][2];
#pragma unroll
            for (int mt = 0; mt < 2; ++mt) {
                int r0 = wr * 32 + mt * 16 + g;
                ah[mt][0] = *(const uint32_t*)(sAh + r0 * RS + kb);
                ah[mt][1] = *(const uint32_t*)(sAh + (r0 + 8) * RS + kb);
                ah[mt][2] = *(const uint32_t*)(sAh + r0 * RS + kb + 16);
                ah[mt][3] = *(const uint32_t*)(sAh + (r0 + 8) * RS + kb + 16);
                al[mt][0] = *(const uint32_t*)(sAl + r0 * RS + kb);
                al[mt][1] = *(const uint32_t*)(sAl + (r0 + 8) * RS + kb);
                al[mt][2] = *(const uint32_t*)(sAl + r0 * RS + kb + 16);
                al[mt][3] = *(const uint32_t*)(sAl + (r0 + 8) * RS + kb + 16);
            }
#pragma unroll
            for (int nt = 0; nt < 8; ++nt) {
                int nr = wc * 64 + nt * 8 + g;
                bh[nt][0] = *(const uint32_t*)(sBh + nr * RS + kb);
                bh[nt][1] = *(const uint32_t*)(sBh + nr * RS + kb + 16);
                bl[nt][0] = *(const uint32_t*)(sBl + nr * RS + kb);
                bl[nt][1] = *(const uint32_t*)(sBl + nr * RS + kb + 16);
            }
#pragma unroll
            for (int mt = 0; mt < 2; ++mt)
#pragma unroll
                for (int nt = 0; nt < 8; ++nt) {
                    mma16816(acc[mt][nt], ah[mt], bh[nt]);
                    mma16816(acc[mt][nt], ah[mt], bl[nt]);
                    mma16816(acc[mt][nt], al[mt], bh[nt]);
                }
        }
    }

    // epilogue
#pragma unroll
    for (int mt = 0; mt < 2; ++mt) {
#pragma unroll
        for (int nt = 0; nt < 8; ++nt) {
            int col = n0 + wc * 64 + nt * 8 + tg * 2;
            float b0 = bias[col], b1 = bias[col + 1];
            int r0 = m0 + wr * 32 + mt * 16 + g;
            float2* p0 = (float2*)(C + (size_t)r0 * Nout + col);
            float2* p1 = (float2*)(C + (size_t)(r0 + 8) * Nout + col);
            *p0 = make_float2(acc[mt][nt][0] + b0, acc[mt][nt][1] + b1);
            *p1 = make_float2(acc[mt][nt][2] + b0, acc[mt][nt][3] + b1);
        }
    }
}

// ---- kernel: windowed cosine attention ----
__global__ void __launch_bounds__(64) attn_kernel(const float* __restrict__ Q,
                                                  const float* __restrict__ KVp,
                                                  const float* __restrict__ bias,
                                                  const float* __restrict__ tau,
                                                  __nv_bfloat16* __restrict__ Ohi,
                                                  __nv_bfloat16* __restrict__ Olo) {
    __shared__ __align__(16) float Ks[64][32], Vs[64][32];
    __shared__ float kns[64];
    int b = blockIdx.x >> 4, h = blockIdx.x & 15;
    int i = threadIdx.x;
    size_t row = (size_t)b * 64 + i;

    const float scale = 0.17677669529663687f;  // 32^-0.5
    float4 q4[8];
    float qn2 = 0.f, kn2 = 0.f;
    {
        const float* qp = Q + row * 512 + h * 32;
        const float* kp = KVp + row * 1024 + h * 32;
        const float* vp = kp + 512;
#pragma unroll
        for (int t = 0; t < 8; ++t) {
            float4 v = *(const float4*)(qp + t * 4);
            v.x *= scale; v.y *= scale; v.z *= scale; v.w *= scale;
            q4[t] = v;
            qn2 += v.x * v.x + v.y * v.y + v.z * v.z + v.w * v.w;
            float4 kk = *(const float4*)(kp + t * 4);
            *(float4*)&Ks[i][t * 4] = kk;
            kn2 += kk.x * kk.x + kk.y * kk.y + kk.z * kk.z + kk.w * kk.w;
            *(float4*)&Vs[i][t * 4] = *(const float4*)(vp + t * 4);
        }
        kns[i] = sqrtf(kn2);
    }
    float qn = sqrtf(qn2);
    __syncthreads();

    const float* bp = bias + h * 4096 + i * 64;
    const float* tp = tau + h * 4096 + i * 64;
    float a[64];
#pragma unroll
    for (int j = 0; j < 64; ++j) {
        float dot = 0.f;
#pragma unroll
        for (int t = 0; t < 8; ++t) {
            float4 k = *(const float4*)&Ks[j][t * 4];
            dot += q4[t].x * k.x + q4[t].y * k.y + q4[t].z * k.z + q4[t].w * k.w;
        }
        float den = fmaxf(qn * kns[j], 1e-6f);
        float tv = fmaxf(tp[j], 0.01f);
        a[j] = dot / den / tv + bp[j];
    }
    float mx = -1e30f;
#pragma unroll
    for (int j = 0; j < 64; ++j) mx = fmaxf(mx, a[j]);
    float s = 0.f;
#pragma unroll
    for (int j = 0; j < 64; ++j) { a[j] = __expf(a[j] - mx); s += a[j]; }
    float inv = 1.f / s;
#pragma unroll
    for (int j = 0; j < 64; ++j) a[j] *= inv;

    size_t ooff = row * 512 + h * 32;
#pragma unroll
    for (int t = 0; t < 8; ++t) {
        float4 o = make_float4(0.f, 0.f, 0.f, 0.f);
#pragma unroll
        for (int j = 0; j < 64; ++j) {
            float4 v = *(const float4*)&Vs[j][t * 4];
            o.x += a[j] * v.x; o.y += a[j] * v.y; o.z += a[j] * v.z; o.w += a[j] * v.w;
        }
        uint32_t h0, h1, l0, l1;
        split_pack2(o.x, o.y, h0, l0);
        split_pack2(o.z, o.w, h1, l1);
        *(uint2*)(Ohi + ooff + t * 4) = make_uint2(h0, h1);
        *(uint2*)(Olo + ooff + t * 4) = make_uint2(l0, l1);
    }
}

// ---- launch ----
extern "C" void kernel_launch(void* const* d_in, const int* in_sizes, int n_in,
                              void* d_out, int out_size) {
    const float* x      = (const float*)d_in[0];
    const float* KV     = (const float*)d_in[1];
    const float* q_w    = (const float*)d_in[2];
    const float* q_b    = (const float*)d_in[3];
    const float* kv_w   = (const float*)d_in[4];
    const float* kv_b   = (const float*)d_in[5];
    const float* proj_w = (const float*)d_in[6];
    const float* proj_b = (const float*)d_in[7];
    const float* cpb_w1 = (const float*)d_in[8];
    const float* cpb_b1 = (const float*)d_in[9];
    const float* cpb_w2 = (const float*)d_in[10];
    const float* cpb_b2 = (const float*)d_in[11];
    const float* tau    = (const float*)d_in[12];

    void *ahi, *alo, *Qp, *KVp, *wqh, *wql, *wkh, *wkl, *wph, *wpl, *bp;
    cudaGetSymbolAddress(&ahi, g_ahi);   cudaGetSymbolAddress(&alo, g_alo);
    cudaGetSymbolAddress(&Qp,  g_Q);     cudaGetSymbolAddress(&KVp, g_KV);
    cudaGetSymbolAddress(&wqh, g_wq_hi); cudaGetSymbolAddress(&wql, g_wq_lo);
    cudaGetSymbolAddress(&wkh, g_wkv_hi);cudaGetSymbolAddress(&wkl, g_wkv_lo);
    cudaGetSymbolAddress(&wph, g_wp_hi); cudaGetSymbolAddress(&wpl, g_wp_lo);
    cudaGetSymbolAddress(&bp,  g_bias);

    cpb_kernel<<<64, 64>>>(cpb_w1, cpb_b1, cpb_w2, cpb_b2, (float*)bp);
    wsplit_kernel<<<(CDIM*CDIM)/256, 256>>>(q_w,  (__nv_bfloat16*)wqh, (__nv_bfloat16*)wql, CDIM, CDIM*CDIM);
    wsplit_kernel<<<(2*CDIM*CDIM)/256, 256>>>(kv_w, (__nv_bfloat16*)wkh, (__nv_bfloat16*)wkl, 2*CDIM, 2*CDIM*CDIM);
    wsplit_kernel<<<(CDIM*CDIM)/256, 256>>>(proj_w,(__nv_bfloat16*)wph, (__nv_bfloat16*)wpl, CDIM, CDIM*CDIM);

    int n4 = MROWS * CDIM / 4;
    split_kernel<<<n4 / 256, 256>>>(x, (__nv_bfloat16*)ahi, (__nv_bfloat16*)alo, n4);
    gemm_tc<<<dim3(4, 512), 256>>>((__nv_bfloat16*)ahi, (__nv_bfloat16*)alo,
        (__nv_bfloat16*)wqh, (__nv_bfloat16*)wql, q_b, (float*)Qp, 512);

    split_kernel<<<n4 / 256, 256>>>(KV, (__nv_bfloat16*)ahi, (__nv_bfloat16*)alo, n4);
    gemm_tc<<<dim3(8, 512), 256>>>((__nv_bfloat16*)ahi, (__nv_bfloat16*)alo,
        (__nv_bfloat16*)wkh, (__nv_bfloat16*)wkl, kv_b, (float*)KVp, 1024);

    attn_kernel<<<BATCH * HEADS, 64>>>((const float*)Qp, (const float*)KVp,
        (const float*)bp, tau, (__nv_bfloat16*)ahi, (__nv_bfloat16*)alo);

    gemm_tc<<<dim3(4, 512), 256>>>((__nv_bfloat16*)ahi, (__nv_bfloat16*)alo,
        (__nv_bfloat16*)wph, (__nv_bfloat16*)wpl, proj_b, (float*)d_out, 512);
}

// round 16
// speedup vs baseline: 1.2112x; 1.2112x over previous
#include <cuda_runtime.h>
#include <cuda_bf16.h>
#include <cstdint>

#define HEADS 16
#define NTOK  64
#define CDIM  512
#define BATCH 1024
#define MROWS (BATCH*NTOK)

// ---- device scratch ----
__device__ __nv_bfloat16 g_ahi[MROWS*CDIM];
__device__ __nv_bfloat16 g_alo[MROWS*CDIM];
__device__ float         g_Q  [(size_t)MROWS*CDIM];
__device__ float         g_KV [(size_t)MROWS*2*CDIM];
__device__ __nv_bfloat16 g_wq_hi [CDIM*CDIM];
__device__ __nv_bfloat16 g_wq_lo [CDIM*CDIM];
__device__ __nv_bfloat16 g_wkv_hi[2*CDIM*CDIM];
__device__ __nv_bfloat16 g_wkv_lo[2*CDIM*CDIM];
__device__ __nv_bfloat16 g_wp_hi [CDIM*CDIM];
__device__ __nv_bfloat16 g_wp_lo [CDIM*CDIM];
__device__ float         g_bias[HEADS*NTOK*NTOK];

__device__ __forceinline__ uint32_t smem_u32(const void* p) {
    uint32_t a;
    asm("{ .reg .u64 t; cvta.to.shared.u64 t, %1; cvt.u32.u64 %0, t; }" : "=r"(a) : "l"(p));
    return a;
}

#define CP_A16(dst, src) asm volatile("cp.async.cg.shared.global [%0], [%1], 16;" :: "r"(dst), "l"(src))
#define CP_COMMIT()      asm volatile("cp.async.commit_group;" ::: "memory")
#define CP_WAIT(n)       asm volatile("cp.async.wait_group %0;" :: "n"(n) : "memory")

__device__ __forceinline__ void split_pack2(float a, float b, uint32_t& hp, uint32_t& lp) {
    __nv_bfloat16 ha = __float2bfloat16(a), hb = __float2bfloat16(b);
    __nv_bfloat16 la = __float2bfloat16(a - __bfloat162float(ha));
    __nv_bfloat16 lb = __float2bfloat16(b - __bfloat162float(hb));
    hp = (uint32_t)__bfloat16_as_ushort(ha) | ((uint32_t)__bfloat16_as_ushort(hb) << 16);
    lp = (uint32_t)__bfloat16_as_ushort(la) | ((uint32_t)__bfloat16_as_ushort(lb) << 16);
}

__device__ __forceinline__ void mma16816(float* d, const uint32_t* a, const uint32_t* b) {
    asm volatile(
        "mma.sync.aligned.m16n8k16.row.col.f32.bf16.bf16.f32 "
        "{%0,%1,%2,%3}, {%4,%5,%6,%7}, {%8,%9}, {%0,%1,%2,%3};"
        : "+f"(d[0]), "+f"(d[1]), "+f"(d[2]), "+f"(d[3])
        : "r"(a[0]), "r"(a[1]), "r"(a[2]), "r"(a[3]), "r"(b[0]), "r"(b[1]));
}

// ---- kernel: CPB bias MLP (batch independent) ----
__global__ void __launch_bounds__(64) cpb_kernel(const float* __restrict__ w1, const float* __restrict__ b1,
                                                 const float* __restrict__ w2, const float* __restrict__ b2,
                                                 float* __restrict__ bias) {
    int p = blockIdx.x * 64 + threadIdx.x;
    int i = p >> 6, j = p & 63;
    float r0 = (float)((i >> 3) - (j >> 3));
    float r1 = (float)((i & 7) - (j & 7));
    float v0 = (r0 > 0.f ? 1.f : (r0 < 0.f ? -1.f : 0.f)) * log1pf(fabsf(r0));
    float v1 = (r1 > 0.f ? 1.f : (r1 < 0.f ? -1.f : 0.f)) * log1pf(fabsf(r1));
    float acc[16];
#pragma unroll
    for (int h = 0; h < 16; ++h) acc[h] = b2[h];
    for (int c = 0; c < 256; ++c) {
        float hv = fmaxf(v0 * w1[c] + v1 * w1[256 + c] + b1[c], 0.f);
#pragma unroll
        for (int h = 0; h < 16; ++h) acc[h] += hv * w2[c * 16 + h];
    }
#pragma unroll
    for (int h = 0; h < 16; ++h) bias[h * 4096 + p] = acc[h];
}

// ---- kernel: fp32 -> bf16 hi/lo split ----
__global__ void __launch_bounds__(256) split_kernel(const float* __restrict__ X,
                                                    __nv_bfloat16* __restrict__ Hi,
                                                    __nv_bfloat16* __restrict__ Lo, int n4) {
    int idx = blockIdx.x * 256 + threadIdx.x;
    if (idx >= n4) return;
    float4 v = ((const float4*)X)[idx];
    uint32_t h0, h1, l0, l1;
    split_pack2(v.x, v.y, h0, l0);
    split_pack2(v.z, v.w, h1, l1);
    ((uint2*)Hi)[idx] = make_uint2(h0, h1);
    ((uint2*)Lo)[idx] = make_uint2(l0, l1);
}

// ---- kernel: weight transpose + split: WT[n][k] = W[k][n] ----
__global__ void __launch_bounds__(256) wsplit_kernel(const float* __restrict__ W,
                                                     __nv_bfloat16* __restrict__ Hi,
                                                     __nv_bfloat16* __restrict__ Lo, int Nout, int total) {
    int idx = blockIdx.x * 256 + threadIdx.x;
    if (idx >= total) return;
    int k = idx & (CDIM - 1), n = idx >> 9;
    float v = W[(size_t)k * Nout + n];
    __nv_bfloat16 hv = __float2bfloat16(v);
    Hi[idx] = hv;
    Lo[idx] = __float2bfloat16(v - __bfloat162float(hv));
}

// ---- kernel: split-bf16 HMMA GEMM, tile 128x128, Kc=32, K=512, cp.async double-buffered ----
#define RS   80                      // smem row stride bytes (64B data + 16B pad)
#define MATB (128*RS)                // one matrix tile: 10240 B
#define BUFB (4*MATB)                // one stage (Ahi,Alo,Bhi,Blo): 40960 B
#define GSM  (2*BUFB)                // 81920 B dynamic smem

__global__ void __launch_bounds__(256, 2) gemm_tc(const __nv_bfloat16* __restrict__ Ahi,
                                                  const __nv_bfloat16* __restrict__ Alo,
                                                  const __nv_bfloat16* __restrict__ Bhi,
                                                  const __nv_bfloat16* __restrict__ Blo,
                                                  const float* __restrict__ bias,
                                                  float* __restrict__ C, int Nout) {
    extern __shared__ __align__(16) char smem[];
    uint32_t sb = smem_u32(smem);

    int tid = threadIdx.x, wid = tid >> 5, lane = tid & 31;
    int wr = wid & 3, wc = wid >> 2;            // warp row (M/32), warp col (N/64)
    int g = lane >> 2, tg = lane & 3;
    int n0 = blockIdx.x * 128, m0 = blockIdx.y * 128;

    // per-thread staging coords (same for both iters)
    int r0i = tid >> 2, c16 = tid & 3;          // it=0: rows 0..63
    int r1i = r0i + 64;                         //  it=1: rows 64..127

    float acc[2][8][4];
#pragma unroll
    for (int mt = 0; mt < 2; ++mt)
#pragma unroll
        for (int nt = 0; nt < 8; ++nt)
#pragma unroll
            for (int c = 0; c < 4; ++c) acc[mt][nt][c] = 0.f;

    // ---- prefetch helper (as a lambda-free macro-style block) ----
#define PREFETCH(STAGE, K0) do {                                               \
    uint32_t bs = sb + (STAGE) * BUFB;                                         \
    size_t ga0 = (size_t)(m0 + r0i) * CDIM + (K0) + c16 * 8;                   \
    size_t ga1 = (size_t)(m0 + r1i) * CDIM + (K0) + c16 * 8;                   \
    size_t gb0 = (size_t)(n0 + r0i) * CDIM + (K0) + c16 * 8;                   \
    size_t gb1 = (size_t)(n0 + r1i) * CDIM + (K0) + c16 * 8;                   \
    uint32_t s0 = r0i * RS + c16 * 16, s1 = r1i * RS + c16 * 16;               \
    CP_A16(bs + s0,            Ahi + ga0);                                     \
    CP_A16(bs + s1,            Ahi + ga1);                                     \
    CP_A16(bs + MATB   + s0,   Alo + ga0);                                     \
    CP_A16(bs + MATB   + s1,   Alo + ga1);                                     \
    CP_A16(bs + 2*MATB + s0,   Bhi + gb0);                                     \
    CP_A16(bs + 2*MATB + s1,   Bhi + gb1);                                     \
    CP_A16(bs + 3*MATB + s0,   Blo + gb0);                                     \
    CP_A16(bs + 3*MATB + s1,   Blo + gb1);                                     \
} while (0)

    PREFETCH(0, 0);
    CP_COMMIT();

    for (int ch = 0; ch < 16; ++ch) {
        if (ch < 15) {
            PREFETCH((ch + 1) & 1, (ch + 1) * 32);
            CP_COMMIT();
            CP_WAIT(1);
        } else {
            CP_WAIT(0);
        }
        __syncthreads();

        const char* base = smem + (ch & 1) * BUFB;
        const char* sAh = base;
        const char* sAl = base + MATB;
        const char* sBh = base + 2 * MATB;
        const char* sBl = base + 3 * MATB;

#pragma unroll
        for (int ks = 0; ks < 2; ++ks) {
            int kb = ks * 32 + tg * 4;
            uint32_t ah[2][4], al[2][4];
#pragma unroll
            for (int mt = 0; mt < 2; ++mt) {
                int rr = wr * 32 + mt * 16 + g;
                ah[mt][0] = *(const uint32_t*)(sAh + rr * RS + kb);
                ah[mt][1] = *(const uint32_t*)(sAh + (rr + 8) * RS + kb);
                ah[mt][2] = *(const uint32_t*)(sAh + rr * RS + kb + 16);
                ah[mt][3] = *(const uint32_t*)(sAh + (rr + 8) * RS + kb + 16);
                al[mt][0] = *(const uint32_t*)(sAl + rr * RS + kb);
                al[mt][1] = *(const uint32_t*)(sAl + (rr + 8) * RS + kb);
                al[mt][2] = *(const uint32_t*)(sAl + rr * RS + kb + 16);
                al[mt][3] = *(const uint32_t*)(sAl + (rr + 8) * RS + kb + 16);
            }
#pragma unroll
            for (int nt = 0; nt < 8; ++nt) {
                int nr = wc * 64 + nt * 8 + g;
                uint32_t bh[2], bl[2];
                bh[0] = *(const uint32_t*)(sBh + nr * RS + kb);
                bh[1] = *(const uint32_t*)(sBh + nr * RS + kb + 16);
                bl[0] = *(const uint32_t*)(sBl + nr * RS + kb);
                bl[1] = *(const uint32_t*)(sBl + nr * RS + kb + 16);
                mma16816(acc[0][nt], ah[0], bh);
                mma16816(acc[0][nt], ah[0], bl);
                mma16816(acc[0][nt], al[0], bh);
                mma16816(acc[1][nt], ah[1], bh);
                mma16816(acc[1][nt], ah[1], bl);
                mma16816(acc[1][nt], al[1], bh);
            }
        }
        __syncthreads();
    }
#undef PREFETCH

    // epilogue
#pragma unroll
    for (int mt = 0; mt < 2; ++mt) {
#pragma unroll
        for (int nt = 0; nt < 8; ++nt) {
            int col = n0 + wc * 64 + nt * 8 + tg * 2;
            float b0 = bias[col], b1 = bias[col + 1];
            int rr = m0 + wr * 32 + mt * 16 + g;
            float2* p0 = (float2*)(C + (size_t)rr * Nout + col);
            float2* p1 = (float2*)(C + (size_t)(rr + 8) * Nout + col);
            *p0 = make_float2(acc[mt][nt][0] + b0, acc[mt][nt][1] + b1);
            *p1 = make_float2(acc[mt][nt][2] + b0, acc[mt][nt][3] + b1);
        }
    }
}

// ---- kernel: windowed cosine attention ----
__global__ void __launch_bounds__(64) attn_kernel(const float* __restrict__ Q,
                                                  const float* __restrict__ KVp,
                                                  const float* __restrict__ bias,
                                                  const float* __restrict__ tau,
                                                  __nv_bfloat16* __restrict__ Ohi,
                                                  __nv_bfloat16* __restrict__ Olo) {
    __shared__ __align__(16) float Ks[64][32], Vs[64][32];
    __shared__ float kns[64];
    int b = blockIdx.x >> 4, h = blockIdx.x & 15;
    int i = threadIdx.x;
    size_t row = (size_t)b * 64 + i;

    const float scale = 0.17677669529663687f;  // 32^-0.5
    float4 q4[8];
    float qn2 = 0.f, kn2 = 0.f;
    {
        const float* qp = Q + row * 512 + h * 32;
        const float* kp = KVp + row * 1024 + h * 32;
        const float* vp = kp + 512;
#pragma unroll
        for (int t = 0; t < 8; ++t) {
            float4 v = *(const float4*)(qp + t * 4);
            v.x *= scale; v.y *= scale; v.z *= scale; v.w *= scale;
            q4[t] = v;
            qn2 += v.x * v.x + v.y * v.y + v.z * v.z + v.w * v.w;
            float4 kk = *(const float4*)(kp + t * 4);
            *(float4*)&Ks[i][t * 4] = kk;
            kn2 += kk.x * kk.x + kk.y * kk.y + kk.z * kk.z + kk.w * kk.w;
            *(float4*)&Vs[i][t * 4] = *(const float4*)(vp + t * 4);
        }
        kns[i] = sqrtf(kn2);
    }
    float qn = sqrtf(qn2);
    __syncthreads();

    const float* bp = bias + h * 4096 + i * 64;
    const float* tp = tau + h * 4096 + i * 64;
    float a[64];
#pragma unroll
    for (int j = 0; j < 64; ++j) {
        float dot = 0.f;
#pragma unroll
        for (int t = 0; t < 8; ++t) {
            float4 k = *(const float4*)&Ks[j][t * 4];
            dot += q4[t].x * k.x + q4[t].y * k.y + q4[t].z * k.z + q4[t].w * k.w;
        }
        float den = fmaxf(qn * kns[j], 1e-6f);
        float tv = fmaxf(tp[j], 0.01f);
        a[j] = dot / den / tv + bp[j];
    }
    float mx = -1e30f;
#pragma unroll
    for (int j = 0; j < 64; ++j) mx = fmaxf(mx, a[j]);
    float s = 0.f;
#pragma unroll
    for (int j = 0; j < 64; ++j) { a[j] = __expf(a[j] - mx); s += a[j]; }
    float inv = 1.f / s;
#pragma unroll
    for (int j = 0; j < 64; ++j) a[j] *= inv;

    size_t ooff = row * 512 + h * 32;
#pragma unroll
    for (int t = 0; t < 8; ++t) {
        float4 o = make_float4(0.f, 0.f, 0.f, 0.f);
#pragma unroll
        for (int j = 0; j < 64; ++j) {
            float4 v = *(const float4*)&Vs[j][t * 4];
            o.x += a[j] * v.x; o.y += a[j] * v.y; o.z += a[j] * v.z; o.w += a[j] * v.w;
        }
        uint32_t h0, h1, l0, l1;
        split_pack2(o.x, o.y, h0, l0);
        split_pack2(o.z, o.w, h1, l1);
        *(uint2*)(Ohi + ooff + t * 4) = make_uint2(h0, h1);
        *(uint2*)(Olo + ooff + t * 4) = make_uint2(l0, l1);
    }
}

// ---- launch ----
extern "C" void kernel_launch(void* const* d_in, const int* in_sizes, int n_in,
                              void* d_out, int out_size) {
    const float* x      = (const float*)d_in[0];
    const float* KV     = (const float*)d_in[1];
    const float* q_w    = (const float*)d_in[2];
    const float* q_b    = (const float*)d_in[3];
    const float* kv_w   = (const float*)d_in[4];
    const float* kv_b   = (const float*)d_in[5];
    const float* proj_w = (const float*)d_in[6];
    const float* proj_b = (const float*)d_in[7];
    const float* cpb_w1 = (const float*)d_in[8];
    const float* cpb_b1 = (const float*)d_in[9];
    const float* cpb_w2 = (const float*)d_in[10];
    const float* cpb_b2 = (const float*)d_in[11];
    const float* tau    = (const float*)d_in[12];

    static int smem_set = 0;
    if (!smem_set) {
        cudaFuncSetAttribute(gemm_tc, cudaFuncAttributeMaxDynamicSharedMemorySize, GSM);
        smem_set = 1;
    }

    void *ahi, *alo, *Qp, *KVp, *wqh, *wql, *wkh, *wkl, *wph, *wpl, *bp;
    cudaGetSymbolAddress(&ahi, g_ahi);   cudaGetSymbolAddress(&alo, g_alo);
    cudaGetSymbolAddress(&Qp,  g_Q);     cudaGetSymbolAddress(&KVp, g_KV);
    cudaGetSymbolAddress(&wqh, g_wq_hi); cudaGetSymbolAddress(&wql, g_wq_lo);
    cudaGetSymbolAddress(&wkh, g_wkv_hi);cudaGetSymbolAddress(&wkl, g_wkv_lo);
    cudaGetSymbolAddress(&wph, g_wp_hi); cudaGetSymbolAddress(&wpl, g_wp_lo);
    cudaGetSymbolAddress(&bp,  g_bias);

    cpb_kernel<<<64, 64>>>(cpb_w1, cpb_b1, cpb_w2, cpb_b2, (float*)bp);
    wsplit_kernel<<<(CDIM*CDIM)/256, 256>>>(q_w,  (__nv_bfloat16*)wqh, (__nv_bfloat16*)wql, CDIM, CDIM*CDIM);
    wsplit_kernel<<<(2*CDIM*CDIM)/256, 256>>>(kv_w, (__nv_bfloat16*)wkh, (__nv_bfloat16*)wkl, 2*CDIM, 2*CDIM*CDIM);
    wsplit_kernel<<<(CDIM*CDIM)/256, 256>>>(proj_w,(__nv_bfloat16*)wph, (__nv_bfloat16*)wpl, CDIM, CDIM*CDIM);

    int n4 = MROWS * CDIM / 4;
    split_kernel<<<n4 / 256, 256>>>(x, (__nv_bfloat16*)ahi, (__nv_bfloat16*)alo, n4);
    gemm_tc<<<dim3(4, 512), 256, GSM>>>((__nv_bfloat16*)ahi, (__nv_bfloat16*)alo,
        (__nv_bfloat16*)wqh, (__nv_bfloat16*)wql, q_b, (float*)Qp, 512);

    split_kernel<<<n4 / 256, 256>>>(KV, (__nv_bfloat16*)ahi, (__nv_bfloat16*)alo, n4);
    gemm_tc<<<dim3(8, 512), 256, GSM>>>((__nv_bfloat16*)ahi, (__nv_bfloat16*)alo,
        (__nv_bfloat16*)wkh, (__nv_bfloat16*)wkl, kv_b, (float*)KVp, 1024);

    attn_kernel<<<BATCH * HEADS, 64>>>((const float*)Qp, (const float*)KVp,
        (const float*)bp, tau, (__nv_bfloat16*)ahi, (__nv_bfloat16*)alo);

    gemm_tc<<<dim3(4, 512), 256, GSM>>>((__nv_bfloat16*)ahi, (__nv_bfloat16*)alo,
        (__nv_bfloat16*)wph, (__nv_bfloat16*)wpl, proj_b, (float*)d_out, 512);
}